// round 11
// baseline (speedup 1.0000x reference)
#include <cuda_runtime.h>
#include <cuda_fp16.h>
#include <cstdint>
#include <math.h>

// ---------------------------------------------------------------------------
// Problem constants
// ---------------------------------------------------------------------------
#define TSEQ   2048
#define HID    2048
#define QDIM   4096   // 32 rope-heads * 128
#define KVDIM  1024   // 8 kv heads * 128
#define HD     128
#define NH16   16
#define NKV    8
#define HQ     32

#define ATT_SCALE 0.08838834764831845f   // 1/sqrt(128)

// ---------------------------------------------------------------------------
// Static device scratch (no allocations allowed)
// ---------------------------------------------------------------------------
__device__ float    g_q  [TSEQ * QDIM];
__device__ float    g_k  [TSEQ * KVDIM];
__device__ float    g_v  [TSEQ * KVDIM];
__device__ float    g_qr [TSEQ * QDIM];
__device__ __half   g_kr [TSEQ * KVDIM];
__device__ float    g_att[TSEQ * QDIM];
__device__ __half   g_wqt[QDIM * HID];
__device__ __half   g_wkt[KVDIM * HID];
__device__ __half   g_wvt[KVDIM * HID];
__device__ __half   g_wot[HID * QDIM];
__device__ __half   g_vt [KVDIM * TSEQ];
__device__ float    g_s  [134217728];     // 32 heads * 2048 * 2048 fp32
__device__ unsigned g_rmax[HQ * TSEQ];    // per-head per-row max (encoded)

// ---------------------------------------------------------------------------
// Helpers
// ---------------------------------------------------------------------------
__device__ __forceinline__ uint32_t pk_h2(float a, float b) {
    __half2 h = __floats2half2_rn(a, b);
    return *reinterpret_cast<uint32_t*>(&h);
}

// Monotonic float <-> uint mapping (total order preserved under uint compare)
__device__ __forceinline__ unsigned enc_f(float f) {
    unsigned u = __float_as_uint(f);
    return (u & 0x80000000u) ? ~u : (u | 0x80000000u);
}
__device__ __forceinline__ float dec_f(unsigned u) {
    return (u & 0x80000000u) ? __uint_as_float(u & 0x7FFFFFFFu)
                             : __uint_as_float(~u);
}

__device__ __forceinline__ void mma_f16(
    float& d0, float& d1, float& d2, float& d3,
    uint32_t a0, uint32_t a1, uint32_t a2, uint32_t a3,
    uint32_t b0, uint32_t b1)
{
    asm volatile(
        "mma.sync.aligned.m16n8k16.row.col.f32.f16.f16.f32 "
        "{%0,%1,%2,%3}, {%4,%5,%6,%7}, {%8,%9}, {%0,%1,%2,%3};"
        : "+f"(d0), "+f"(d1), "+f"(d2), "+f"(d3)
        : "r"(a0), "r"(a1), "r"(a2), "r"(a3), "r"(b0), "r"(b1));
}

// ---------------------------------------------------------------------------
// fp16 mma.sync GEMM: C[M,N] = A[M,K] @ B[N,K]^T
// MODE 0: plain (A fp32 -> half SMEM, C fp32)
// MODE 1: plain + per-row max of C published via atomicMax(enc) to rmax
// MODE 2: softmax-fused PV: A-store path applies exp((a - rowmax)*scale),
//         accumulates row sums inline, epilogue normalizes C by 1/rowsum
// 128x128 CTA tile, BK=32, 8 warps, warp tile 64x32. Batched via blockIdx.z.
// ---------------------------------------------------------------------------
#define BM 128
#define BN 128
#define BK 32
#define AWS 20   // half2-word row stride: 16 data + 4 pad (conflict-free frags)

template <int MODE>
__global__ __launch_bounds__(256) void gemm_t(
    const float* __restrict__ A, const __half* __restrict__ B,
    float* __restrict__ C, int K, int lda, int ldb, int ldc,
    long long bsA, long long bsB, long long bsC, int bshift,
    unsigned* __restrict__ rmax)
{
    __shared__ uint32_t As[BM][AWS];
    __shared__ uint32_t Bs[BN][AWS];
    __shared__ float    lsh[BM];          // MODE 2 row sums

    const int z = blockIdx.z;
    A += (long long)z * bsA;
    B += (long long)(z >> bshift) * bsB;
    C += (long long)z * bsC;
    if (MODE != 0) rmax += (long long)z * TSEQ;

    const int tid  = threadIdx.x;
    const int wid  = tid >> 5;
    const int lane = tid & 31;
    const int m0 = blockIdx.y * BM;
    const int n0 = blockIdx.x * BN;

    const int wm = (wid >> 2) * 64;
    const int wn = (wid & 3) * 32;
    const int g  = lane >> 2;
    const int t  = lane & 3;

    float acc[4][4][4];
#pragma unroll
    for (int mt = 0; mt < 4; mt++)
#pragma unroll
        for (int nt = 0; nt < 4; nt++)
#pragma unroll
            for (int r = 0; r < 4; r++) acc[mt][nt][r] = 0.0f;

    // A: 32 rows/pass x 4; 8 threads/row, float4.  B: 64 rows/pass x 2; uint4.
    const int ra = tid >> 3;
    const int ca = (tid & 7) << 2;
    const int rb = tid >> 2;
    const int cb = (tid & 3) << 3;

    // MODE 2: per-thread scaled row maxima + row-sum accumulators
    float ms[4], lsum[4];
    if (MODE == 2) {
#pragma unroll
        for (int p = 0; p < 4; p++) {
            ms[p] = dec_f(rmax[m0 + ra + (p << 5)]) * ATT_SCALE;
            lsum[p] = 0.0f;
        }
    }

    float4 pa[4];
    uint4  pb[2];
#pragma unroll
    for (int p = 0; p < 4; p++)
        pa[p] = *(const float4*)(A + (size_t)(m0 + ra + (p << 5)) * lda + ca);
#pragma unroll
    for (int p = 0; p < 2; p++)
        pb[p] = *(const uint4*)(B + (size_t)(n0 + rb + (p << 6)) * ldb + cb);

#pragma unroll
    for (int p = 0; p < 4; p++) {
        const int r = ra + (p << 5);
        if (MODE == 2) {
            float e0 = __expf(fmaf(pa[p].x, ATT_SCALE, -ms[p]));
            float e1 = __expf(fmaf(pa[p].y, ATT_SCALE, -ms[p]));
            float e2 = __expf(fmaf(pa[p].z, ATT_SCALE, -ms[p]));
            float e3 = __expf(fmaf(pa[p].w, ATT_SCALE, -ms[p]));
            lsum[p] += (e0 + e1) + (e2 + e3);
            As[r][(ca >> 1) + 0] = pk_h2(e0, e1);
            As[r][(ca >> 1) + 1] = pk_h2(e2, e3);
        } else {
            As[r][(ca >> 1) + 0] = pk_h2(pa[p].x, pa[p].y);
            As[r][(ca >> 1) + 1] = pk_h2(pa[p].z, pa[p].w);
        }
    }
#pragma unroll
    for (int p = 0; p < 2; p++) {
        const int r = rb + (p << 6);
        Bs[r][(cb >> 1) + 0] = pb[p].x;
        Bs[r][(cb >> 1) + 1] = pb[p].y;
        Bs[r][(cb >> 1) + 2] = pb[p].z;
        Bs[r][(cb >> 1) + 3] = pb[p].w;
    }
    __syncthreads();

    const int nk = K >> 5;
    for (int kt = 0; kt < nk; kt++) {
        if (kt + 1 < nk) {
            const int k0 = (kt + 1) << 5;
#pragma unroll
            for (int p = 0; p < 4; p++)
                pa[p] = *(const float4*)(A + (size_t)(m0 + ra + (p << 5)) * lda + k0 + ca);
#pragma unroll
            for (int p = 0; p < 2; p++)
                pb[p] = *(const uint4*)(B + (size_t)(n0 + rb + (p << 6)) * ldb + k0 + cb);
        }

#pragma unroll
        for (int kc = 0; kc < 2; kc++) {
            const int kw = kc << 3;
            uint32_t af[4][4], bf[4][2];
#pragma unroll
            for (int mt = 0; mt < 4; mt++) {
                const int r = wm + mt * 16 + g;
                af[mt][0] = As[r    ][kw + t];
                af[mt][1] = As[r + 8][kw + t];
                af[mt][2] = As[r    ][kw + t + 4];
                af[mt][3] = As[r + 8][kw + t + 4];
            }
#pragma unroll
            for (int nt = 0; nt < 4; nt++) {
                const int r = wn + nt * 8 + g;
                bf[nt][0] = Bs[r][kw + t];
                bf[nt][1] = Bs[r][kw + t + 4];
            }
#pragma unroll
            for (int mt = 0; mt < 4; mt++)
#pragma unroll
                for (int nt = 0; nt < 4; nt++)
                    mma_f16(acc[mt][nt][0], acc[mt][nt][1],
                            acc[mt][nt][2], acc[mt][nt][3],
                            af[mt][0], af[mt][1], af[mt][2], af[mt][3],
                            bf[nt][0], bf[nt][1]);
        }
        __syncthreads();

        if (kt + 1 < nk) {
#pragma unroll
            for (int p = 0; p < 4; p++) {
                const int r = ra + (p << 5);
                if (MODE == 2) {
                    float e0 = __expf(fmaf(pa[p].x, ATT_SCALE, -ms[p]));
                    float e1 = __expf(fmaf(pa[p].y, ATT_SCALE, -ms[p]));
                    float e2 = __expf(fmaf(pa[p].z, ATT_SCALE, -ms[p]));
                    float e3 = __expf(fmaf(pa[p].w, ATT_SCALE, -ms[p]));
                    lsum[p] += (e0 + e1) + (e2 + e3);
                    As[r][(ca >> 1) + 0] = pk_h2(e0, e1);
                    As[r][(ca >> 1) + 1] = pk_h2(e2, e3);
                } else {
                    As[r][(ca >> 1) + 0] = pk_h2(pa[p].x, pa[p].y);
                    As[r][(ca >> 1) + 1] = pk_h2(pa[p].z, pa[p].w);
                }
            }
#pragma unroll
            for (int p = 0; p < 2; p++) {
                const int r = rb + (p << 6);
                Bs[r][(cb >> 1) + 0] = pb[p].x;
                Bs[r][(cb >> 1) + 1] = pb[p].y;
                Bs[r][(cb >> 1) + 2] = pb[p].z;
                Bs[r][(cb >> 1) + 3] = pb[p].w;
            }
            __syncthreads();
        }
    }

    // MODE 2: reduce row sums (8 threads per row, contiguous lanes) -> SMEM
    float linv_lo[4], linv_hi[4];
    if (MODE == 2) {
#pragma unroll
        for (int p = 0; p < 4; p++) {
            float v = lsum[p];
            v += __shfl_xor_sync(0xffffffffu, v, 1);
            v += __shfl_xor_sync(0xffffffffu, v, 2);
            v += __shfl_xor_sync(0xffffffffu, v, 4);
            if ((tid & 7) == 0) lsh[ra + (p << 5)] = v;
        }
        __syncthreads();
#pragma unroll
        for (int mt = 0; mt < 4; mt++) {
            linv_lo[mt] = 1.0f / lsh[wm + mt * 16 + g];
            linv_hi[mt] = 1.0f / lsh[wm + mt * 16 + g + 8];
        }
    }

    // Epilogue
#pragma unroll
    for (int mt = 0; mt < 4; mt++) {
        const int row = m0 + wm + mt * 16 + g;
        if (MODE == 2) {
#pragma unroll
            for (int nt = 0; nt < 4; nt++) {
                acc[mt][nt][0] *= linv_lo[mt]; acc[mt][nt][1] *= linv_lo[mt];
                acc[mt][nt][2] *= linv_hi[mt]; acc[mt][nt][3] *= linv_hi[mt];
            }
        }
#pragma unroll
        for (int nt = 0; nt < 4; nt++) {
            const int col = n0 + wn + nt * 8 + 2 * t;
            *(float2*)(C + (size_t)row * ldc + col) =
                make_float2(acc[mt][nt][0], acc[mt][nt][1]);
            *(float2*)(C + (size_t)(row + 8) * ldc + col) =
                make_float2(acc[mt][nt][2], acc[mt][nt][3]);
        }
        if (MODE == 1) {
            float lo = fmaxf(acc[mt][0][0], acc[mt][0][1]);
            float hi = fmaxf(acc[mt][0][2], acc[mt][0][3]);
#pragma unroll
            for (int nt = 1; nt < 4; nt++) {
                lo = fmaxf(lo, fmaxf(acc[mt][nt][0], acc[mt][nt][1]));
                hi = fmaxf(hi, fmaxf(acc[mt][nt][2], acc[mt][nt][3]));
            }
            lo = fmaxf(lo, __shfl_xor_sync(0xffffffffu, lo, 1));
            lo = fmaxf(lo, __shfl_xor_sync(0xffffffffu, lo, 2));
            hi = fmaxf(hi, __shfl_xor_sync(0xffffffffu, hi, 1));
            hi = fmaxf(hi, __shfl_xor_sync(0xffffffffu, hi, 2));
            if (t == 0) {
                atomicMax(rmax + row,     enc_f(lo));
                atomicMax(rmax + row + 8, enc_f(hi));
            }
        }
    }
}

// ---------------------------------------------------------------------------
// rmax init
// ---------------------------------------------------------------------------
__global__ void init_rmax(unsigned* __restrict__ r)
{
    r[blockIdx.x * 256 + threadIdx.x] = enc_f(-1e30f);
}

// ---------------------------------------------------------------------------
// Tiled transpose fp32 -> fp16: out[C][R] = half(in[R][C]^T)
// ---------------------------------------------------------------------------
__global__ void transpose_h(const float* __restrict__ in,
                            __half* __restrict__ out, int R, int C)
{
    __shared__ float t[32][33];
    const int x = blockIdx.x * 32 + threadIdx.x;
    const int y0 = blockIdx.y * 32 + threadIdx.y;
#pragma unroll
    for (int j = 0; j < 32; j += 8)
        t[threadIdx.y + j][threadIdx.x] = in[(size_t)(y0 + j) * C + x];
    __syncthreads();
    const int x2 = blockIdx.y * 32 + threadIdx.x;
    const int y2 = blockIdx.x * 32 + threadIdx.y;
#pragma unroll
    for (int j = 0; j < 32; j += 8)
        out[(size_t)(y2 + j) * R + x2] = __float2half(t[threadIdx.x][threadIdx.y + j]);
}

// ---------------------------------------------------------------------------
// Q rmsnorm (over 256) + rope (fp32 out). grid (TSEQ,16), 256 threads.
// ---------------------------------------------------------------------------
__global__ void qnorm_rope_kernel(
    const float* __restrict__ q, const float* __restrict__ w,
    const float* __restrict__ sinp, const float* __restrict__ cosp,
    float* __restrict__ out)
{
    const int t = blockIdx.x, h = blockIdx.y;
    const int tid = threadIdx.x;
    __shared__ float buf[256];
    __shared__ float red[8];

    float v = q[t * QDIM + h * 256 + tid];
    float ss = v * v;
#pragma unroll
    for (int o = 16; o > 0; o >>= 1) ss += __shfl_down_sync(0xffffffffu, ss, o);
    if ((tid & 31) == 0) red[tid >> 5] = ss;
    __syncthreads();
    if (tid < 8) {
        float s = red[tid];
#pragma unroll
        for (int o = 4; o > 0; o >>= 1) s += __shfl_down_sync(0xffu, s, o);
        if (tid == 0) red[0] = s;
    }
    __syncthreads();
    float inv = rsqrtf(red[0] * (1.0f / 256.0f) + 1e-6f);
    buf[tid] = v * inv * w[tid];
    __syncthreads();

    int sub = tid >> 7, d = tid & 127;
    const float* base = buf + (sub << 7);
    int j = (d < 64) ? d : d - 64;
    float c = cosp[t * 64 + j], s = sinp[t * 64 + j];
    float x1 = base[2 * j], x2 = base[2 * j + 1];
    float o = (d < 64) ? (x1 * c - x2 * s) : (x1 * s + x2 * c);
    out[t * QDIM + (h * 2 + sub) * HD + d] = o;
}

// ---------------------------------------------------------------------------
// K rmsnorm (over 128) + rope, fp16 out. grid (TSEQ,8), 128 threads.
// ---------------------------------------------------------------------------
__global__ void knorm_rope_kernel(
    const float* __restrict__ k, const float* __restrict__ w,
    const float* __restrict__ sinp, const float* __restrict__ cosp,
    __half* __restrict__ out)
{
    const int t = blockIdx.x, h = blockIdx.y;
    const int tid = threadIdx.x;
    __shared__ float buf[128];
    __shared__ float red[4];

    float v = k[t * KVDIM + h * HD + tid];
    float ss = v * v;
#pragma unroll
    for (int o = 16; o > 0; o >>= 1) ss += __shfl_down_sync(0xffffffffu, ss, o);
    if ((tid & 31) == 0) red[tid >> 5] = ss;
    __syncthreads();
    if (tid < 4) {
        float s = red[tid];
#pragma unroll
        for (int o = 2; o > 0; o >>= 1) s += __shfl_down_sync(0xfu, s, o);
        if (tid == 0) red[0] = s;
    }
    __syncthreads();
    float inv = rsqrtf(red[0] * (1.0f / 128.0f) + 1e-6f);
    buf[tid] = v * inv * w[tid];
    __syncthreads();

    int d = tid;
    int j = (d < 64) ? d : d - 64;
    float c = cosp[t * 64 + j], s = sinp[t * 64 + j];
    float x1 = buf[2 * j], x2 = buf[2 * j + 1];
    float o = (d < 64) ? (x1 * c - x2 * s) : (x1 * s + x2 * c);
    out[t * KVDIM + h * HD + d] = __float2half(o);
}

// ---------------------------------------------------------------------------
// Launch
// ---------------------------------------------------------------------------
extern "C" void kernel_launch(void* const* d_in, const int* in_sizes, int n_in,
                              void* d_out, int out_size)
{
    const float* x    = (const float*)d_in[0];
    const float* Wq   = (const float*)d_in[1];
    const float* Wk   = (const float*)d_in[2];
    const float* Wv   = (const float*)d_in[3];
    const float* Wo   = (const float*)d_in[4];
    const float* qw   = (const float*)d_in[5];
    const float* kw   = (const float*)d_in[6];
    const float* sinp = (const float*)d_in[7];
    const float* cosp = (const float*)d_in[8];
    float* out = (float*)d_out;

    float *pq, *pk, *pv, *pqr, *patt, *ps;
    __half *pkr, *pwqt, *pwkt, *pwvt, *pwot, *pvt;
    unsigned* prm;
    cudaGetSymbolAddress((void**)&pq,   g_q);
    cudaGetSymbolAddress((void**)&pk,   g_k);
    cudaGetSymbolAddress((void**)&pv,   g_v);
    cudaGetSymbolAddress((void**)&pqr,  g_qr);
    cudaGetSymbolAddress((void**)&pkr,  g_kr);
    cudaGetSymbolAddress((void**)&patt, g_att);
    cudaGetSymbolAddress((void**)&pwqt, g_wqt);
    cudaGetSymbolAddress((void**)&pwkt, g_wkt);
    cudaGetSymbolAddress((void**)&pwvt, g_wvt);
    cudaGetSymbolAddress((void**)&pwot, g_wot);
    cudaGetSymbolAddress((void**)&pvt,  g_vt);
    cudaGetSymbolAddress((void**)&ps,   g_s);
    cudaGetSymbolAddress((void**)&prm,  g_rmax);

    dim3 tb(32, 8);
    // Weight transposes to [N,K] half
    transpose_h<<<dim3(QDIM / 32, HID / 32), tb>>>(Wq, pwqt, HID, QDIM);
    transpose_h<<<dim3(KVDIM / 32, HID / 32), tb>>>(Wk, pwkt, HID, KVDIM);
    transpose_h<<<dim3(KVDIM / 32, HID / 32), tb>>>(Wv, pwvt, HID, KVDIM);
    transpose_h<<<dim3(HID / 32, QDIM / 32), tb>>>(Wo, pwot, QDIM, HID);

    // rmax init (overlaps transposes' tail)
    init_rmax<<<(HQ * TSEQ) / 256, 256>>>(prm);

    // Projections (A fp32, B fp16)
    gemm_t<0><<<dim3(QDIM / BN, TSEQ / BM, 1), 256>>>(
        x, pwqt, pq, HID, HID, HID, QDIM, 0, 0, 0, 0, prm);
    gemm_t<0><<<dim3(KVDIM / BN, TSEQ / BM, 1), 256>>>(
        x, pwkt, pk, HID, HID, HID, KVDIM, 0, 0, 0, 0, prm);
    gemm_t<0><<<dim3(KVDIM / BN, TSEQ / BM, 1), 256>>>(
        x, pwvt, pv, HID, HID, HID, KVDIM, 0, 0, 0, 0, prm);

    // Norm + rope (K output fp16 -> B operand of S gemm)
    qnorm_rope_kernel<<<dim3(TSEQ, NH16), 256>>>(pq, qw, sinp, cosp, pqr);
    knorm_rope_kernel<<<dim3(TSEQ, NKV), 128>>>(pk, kw, sinp, cosp, pkr);

    // V^T (fp16) for PV gemm B operand
    transpose_h<<<dim3(KVDIM / 32, TSEQ / 32), tb>>>(pv, pvt, TSEQ, KVDIM);

    // S = Q K^T per head (raw logits) + row-max publication
    gemm_t<1><<<dim3(TSEQ / BN, TSEQ / BM, HQ), 256>>>(
        pqr, pkr, ps, HD, QDIM, KVDIM, TSEQ,
        (long long)HD, (long long)HD, (long long)TSEQ * TSEQ, 2, prm);

    // O = softmax(S) V per head — exp+normalize fused into the gemm
    gemm_t<2><<<dim3(HD / BN, TSEQ / BM, HQ), 256>>>(
        ps, pvt, patt, TSEQ, TSEQ, TSEQ, QDIM,
        (long long)TSEQ * TSEQ, (long long)HD * TSEQ, (long long)HD, 2, prm);

    // Output projection
    gemm_t<0><<<dim3(HID / BN, TSEQ / BM, 1), 256>>>(
        patt, pwot, out, QDIM, QDIM, QDIM, HID, 0, 0, 0, 0, prm);
}

// round 12
// speedup vs baseline: 1.2473x; 1.2473x over previous
#include <cuda_runtime.h>
#include <cuda_fp16.h>
#include <cstdint>
#include <math.h>

// ---------------------------------------------------------------------------
// Problem constants
// ---------------------------------------------------------------------------
#define TSEQ   2048
#define HID    2048
#define QDIM   4096   // 32 rope-heads * 128
#define KVDIM  1024   // 8 kv heads * 128
#define HD     128
#define NH16   16
#define NKV    8
#define HQ     32

#define ATT_SCALE 0.08838834764831845f   // 1/sqrt(128)

// ---------------------------------------------------------------------------
// Static device scratch (no allocations allowed)
// ---------------------------------------------------------------------------
__device__ __half   g_x16[TSEQ * HID];
__device__ float    g_q  [TSEQ * QDIM];
__device__ float    g_k  [TSEQ * KVDIM];
__device__ float    g_v  [TSEQ * KVDIM];
__device__ __half   g_qr [TSEQ * QDIM];
__device__ __half   g_kr [TSEQ * KVDIM];
__device__ __half   g_att[TSEQ * QDIM];
__device__ __half   g_wqt[QDIM * HID];
__device__ __half   g_wkt[KVDIM * HID];
__device__ __half   g_wvt[KVDIM * HID];
__device__ __half   g_wot[HID * QDIM];
__device__ __half   g_vt [KVDIM * TSEQ];
__device__ float    g_s  [134217728];            // 32 * 2048 * 2048 fp32 S
__device__ __half   g_p  [134217728];            // 32 * 2048 * 2048 fp16 P

// ---------------------------------------------------------------------------
// Helpers
// ---------------------------------------------------------------------------
__device__ __forceinline__ uint32_t pk_h2(float a, float b) {
    __half2 h = __floats2half2_rn(a, b);
    return *reinterpret_cast<uint32_t*>(&h);
}

__device__ __forceinline__ uint32_t smem_u32(const void* p) {
    uint32_t a;
    asm("{ .reg .u64 t; cvta.to.shared.u64 t, %1; cvt.u32.u64 %0, t; }"
        : "=r"(a) : "l"(p));
    return a;
}

__device__ __forceinline__ void mma_f16(
    float& d0, float& d1, float& d2, float& d3,
    uint32_t a0, uint32_t a1, uint32_t a2, uint32_t a3,
    uint32_t b0, uint32_t b1)
{
    asm volatile(
        "mma.sync.aligned.m16n8k16.row.col.f32.f16.f16.f32 "
        "{%0,%1,%2,%3}, {%4,%5,%6,%7}, {%8,%9}, {%0,%1,%2,%3};"
        : "+f"(d0), "+f"(d1), "+f"(d2), "+f"(d3)
        : "r"(a0), "r"(a1), "r"(a2), "r"(a3), "r"(b0), "r"(b1));
}

__device__ __forceinline__ void ldsm4(
    uint32_t& r0, uint32_t& r1, uint32_t& r2, uint32_t& r3, uint32_t addr)
{
    asm volatile(
        "ldmatrix.sync.aligned.m8n8.x4.shared.b16 {%0,%1,%2,%3}, [%4];"
        : "=r"(r0), "=r"(r1), "=r"(r2), "=r"(r3) : "r"(addr));
}

__device__ __forceinline__ void cp16(uint32_t dst, const void* src) {
    asm volatile("cp.async.cg.shared.global [%0], [%1], 16;"
                 :: "r"(dst), "l"(src));
}
#define CP_COMMIT() asm volatile("cp.async.commit_group;" ::: "memory")
#define CP_WAIT0()  asm volatile("cp.async.wait_group 0;" ::: "memory")
#define CP_WAIT1()  asm volatile("cp.async.wait_group 1;" ::: "memory")

// ---------------------------------------------------------------------------
// All-fp16 mma.sync GEMM: C[M,N] = A[M,K] @ B[N,K]^T
// A, B row-major fp16 (K-major). 128x128 CTA tile, BK=32, 8 warps.
// cp.async 2-stage double buffer; ldmatrix.x4 fragment loads.
// OUTH=1 -> C stored fp16, else fp32. Batched via blockIdx.z.
// M, N multiples of 128; K multiple of 32.
// ---------------------------------------------------------------------------
#define BM 128
#define BN 128
#define AWS 20   // half2-word row stride: 16 data + 4 pad
#define GEMM_SMEM ((2 * BM * AWS + 2 * BN * AWS) * 4)   // 81920 B

template <int OUTH>
__global__ __launch_bounds__(256) void gemm_h(
    const __half* __restrict__ A, const __half* __restrict__ B,
    void* __restrict__ Cv, int K, int lda, int ldb, int ldc,
    long long bsA, long long bsB, long long bsC, int bshift)
{
    extern __shared__ uint32_t sm[];

    const int z = blockIdx.z;
    A += (long long)z * bsA;
    B += (long long)(z >> bshift) * bsB;

    const int tid  = threadIdx.x;
    const int wid  = tid >> 5;
    const int lane = tid & 31;
    const int m0 = blockIdx.y * BM;
    const int n0 = blockIdx.x * BN;

    const int wm = (wid >> 2) * 64;
    const int wn = (wid & 3) * 32;
    const int g  = lane >> 2;
    const int t  = lane & 3;

    const uint32_t smb = smem_u32(sm);
    const uint32_t bs_off = 2 * BM * AWS * 4;      // byte offset of Bs region

    // ldmatrix lane address components
    const int l7  = lane & 7;
    const int sel = lane >> 3;
    const uint32_t a_lane = ((l7 + ((sel & 1) << 3)) * AWS + ((sel >> 1) << 2)) * 4;
    const uint32_t b_lane = ((l7 + ((sel >> 1) << 3)) * AWS + ((sel & 1) << 2)) * 4;

    float acc[4][4][4];
#pragma unroll
    for (int mt = 0; mt < 4; mt++)
#pragma unroll
        for (int nt = 0; nt < 4; nt++)
#pragma unroll
            for (int r = 0; r < 4; r++) acc[mt][nt][r] = 0.0f;

    // cp.async tile load: 512 16B chunks per operand; 2 per thread each
    const int r0c = tid >> 2;          // rows for chunk set 0 (+64 for set 1)
    const int off = (tid & 3);         // 16B unit within 64B row

    // prologue: load tile 0 into buffer 0
    {
        const uint32_t as_u = smb;
        const uint32_t bs_u = smb + bs_off;
#pragma unroll
        for (int i = 0; i < 2; i++) {
            const int row = r0c + (i << 6);
            const uint32_t d = ((row * AWS + (off << 2)) << 2);
            cp16(as_u + d, A + (size_t)(m0 + row) * lda + (off << 3));
            cp16(bs_u + d, B + (size_t)(n0 + row) * ldb + (off << 3));
        }
    }
    CP_COMMIT();

    const int nk = K >> 5;
    for (int kt = 0; kt < nk; kt++) {
        const int b = kt & 1;
        if (kt + 1 < nk) {
            const int nb = b ^ 1;
            const int k0 = (kt + 1) << 5;
            const uint32_t as_u = smb + nb * BM * AWS * 4;
            const uint32_t bs_u = smb + bs_off + nb * BN * AWS * 4;
#pragma unroll
            for (int i = 0; i < 2; i++) {
                const int row = r0c + (i << 6);
                const uint32_t d = ((row * AWS + (off << 2)) << 2);
                cp16(as_u + d, A + (size_t)(m0 + row) * lda + k0 + (off << 3));
                cp16(bs_u + d, B + (size_t)(n0 + row) * ldb + k0 + (off << 3));
            }
            CP_COMMIT();
            CP_WAIT1();
        } else {
            CP_WAIT0();
        }
        __syncthreads();

        const uint32_t as_b = smb + b * BM * AWS * 4;
        const uint32_t bs_b = smb + bs_off + b * BN * AWS * 4;

#pragma unroll
        for (int kc = 0; kc < 2; kc++) {
            const uint32_t kw = (kc * 8) * 4;   // byte offset of k-chunk
            uint32_t af[4][4], bf[4][2];
#pragma unroll
            for (int mt = 0; mt < 4; mt++)
                ldsm4(af[mt][0], af[mt][1], af[mt][2], af[mt][3],
                      as_b + ((wm + mt * 16) * AWS) * 4 + kw + a_lane);
#pragma unroll
            for (int np = 0; np < 2; np++)
                ldsm4(bf[2 * np][0], bf[2 * np][1],
                      bf[2 * np + 1][0], bf[2 * np + 1][1],
                      bs_b + ((wn + np * 16) * AWS) * 4 + kw + b_lane);
#pragma unroll
            for (int mt = 0; mt < 4; mt++)
#pragma unroll
                for (int nt = 0; nt < 4; nt++)
                    mma_f16(acc[mt][nt][0], acc[mt][nt][1],
                            acc[mt][nt][2], acc[mt][nt][3],
                            af[mt][0], af[mt][1], af[mt][2], af[mt][3],
                            bf[nt][0], bf[nt][1]);
        }
        __syncthreads();
    }

    // Epilogue
    if (OUTH) {
        __half* C = (__half*)Cv + (long long)z * bsC;
#pragma unroll
        for (int mt = 0; mt < 4; mt++) {
            const int row = m0 + wm + mt * 16 + g;
#pragma unroll
            for (int nt = 0; nt < 4; nt++) {
                const int col = n0 + wn + nt * 8 + 2 * t;
                *(uint32_t*)(C + (size_t)row * ldc + col) =
                    pk_h2(acc[mt][nt][0], acc[mt][nt][1]);
                *(uint32_t*)(C + (size_t)(row + 8) * ldc + col) =
                    pk_h2(acc[mt][nt][2], acc[mt][nt][3]);
            }
        }
    } else {
        float* C = (float*)Cv + (long long)z * bsC;
#pragma unroll
        for (int mt = 0; mt < 4; mt++) {
            const int row = m0 + wm + mt * 16 + g;
#pragma unroll
            for (int nt = 0; nt < 4; nt++) {
                const int col = n0 + wn + nt * 8 + 2 * t;
                *(float2*)(C + (size_t)row * ldc + col) =
                    make_float2(acc[mt][nt][0], acc[mt][nt][1]);
                *(float2*)(C + (size_t)(row + 8) * ldc + col) =
                    make_float2(acc[mt][nt][2], acc[mt][nt][3]);
            }
        }
    }
}

// ---------------------------------------------------------------------------
// fp32 -> fp16 convert (x), vectorized
// ---------------------------------------------------------------------------
__global__ void cvt16(const float* __restrict__ in, __half* __restrict__ out)
{
    const int i = (blockIdx.x * 256 + threadIdx.x) << 2;
    float4 v = *(const float4*)(in + i);
    uint2 o = make_uint2(pk_h2(v.x, v.y), pk_h2(v.z, v.w));
    *(uint2*)(out + i) = o;
}

// ---------------------------------------------------------------------------
// Tiled transpose fp32 -> fp16: out[C][R] = half(in[R][C]^T)
// ---------------------------------------------------------------------------
__global__ void transpose_h(const float* __restrict__ in,
                            __half* __restrict__ out, int R, int C)
{
    __shared__ float t[32][33];
    const int x = blockIdx.x * 32 + threadIdx.x;
    const int y0 = blockIdx.y * 32 + threadIdx.y;
#pragma unroll
    for (int j = 0; j < 32; j += 8)
        t[threadIdx.y + j][threadIdx.x] = in[(size_t)(y0 + j) * C + x];
    __syncthreads();
    const int x2 = blockIdx.y * 32 + threadIdx.x;
    const int y2 = blockIdx.x * 32 + threadIdx.y;
#pragma unroll
    for (int j = 0; j < 32; j += 8)
        out[(size_t)(y2 + j) * R + x2] = __float2half(t[threadIdx.x][threadIdx.y + j]);
}

// ---------------------------------------------------------------------------
// Row softmax: read fp32 S, write fp16 P (scale folded). 1 warp / row.
// ---------------------------------------------------------------------------
__global__ __launch_bounds__(256) void softmax_kernel(
    const float* __restrict__ S, __half* __restrict__ P)
{
    const int row = blockIdx.x * 8 + (threadIdx.x >> 5);
    const int lane = threadIdx.x & 31;
    const float* p = S + (size_t)row * 2048 + lane * 4;
    __half* q = P + (size_t)row * 2048 + lane * 4;

    float4 v[16];
#pragma unroll
    for (int w = 0; w < 16; w++) v[w] = *(const float4*)(p + w * 128);

    float m = -1e30f;
#pragma unroll
    for (int w = 0; w < 16; w++)
        m = fmaxf(m, fmaxf(fmaxf(v[w].x, v[w].y), fmaxf(v[w].z, v[w].w)));
#pragma unroll
    for (int o = 16; o > 0; o >>= 1)
        m = fmaxf(m, __shfl_xor_sync(0xffffffffu, m, o));

    const float ms = m * ATT_SCALE;
    float sum = 0.0f;
#pragma unroll
    for (int w = 0; w < 16; w++) {
        v[w].x = __expf(fmaf(v[w].x, ATT_SCALE, -ms));
        v[w].y = __expf(fmaf(v[w].y, ATT_SCALE, -ms));
        v[w].z = __expf(fmaf(v[w].z, ATT_SCALE, -ms));
        v[w].w = __expf(fmaf(v[w].w, ATT_SCALE, -ms));
        sum += (v[w].x + v[w].y) + (v[w].z + v[w].w);
    }
#pragma unroll
    for (int o = 16; o > 0; o >>= 1)
        sum += __shfl_xor_sync(0xffffffffu, sum, o);

    const float inv = 1.0f / sum;
#pragma unroll
    for (int w = 0; w < 16; w++) {
        uint2 o2 = make_uint2(pk_h2(v[w].x * inv, v[w].y * inv),
                              pk_h2(v[w].z * inv, v[w].w * inv));
        *(uint2*)(q + w * 128) = o2;
    }
}

// ---------------------------------------------------------------------------
// Q rmsnorm (over 256) + rope, fp16 out. grid (TSEQ,16), 256 threads.
// ---------------------------------------------------------------------------
__global__ void qnorm_rope_kernel(
    const float* __restrict__ q, const float* __restrict__ w,
    const float* __restrict__ sinp, const float* __restrict__ cosp,
    __half* __restrict__ out)
{
    const int t = blockIdx.x, h = blockIdx.y;
    const int tid = threadIdx.x;
    __shared__ float buf[256];
    __shared__ float red[8];

    float v = q[t * QDIM + h * 256 + tid];
    float ss = v * v;
#pragma unroll
    for (int o = 16; o > 0; o >>= 1) ss += __shfl_down_sync(0xffffffffu, ss, o);
    if ((tid & 31) == 0) red[tid >> 5] = ss;
    __syncthreads();
    if (tid < 8) {
        float s = red[tid];
#pragma unroll
        for (int o = 4; o > 0; o >>= 1) s += __shfl_down_sync(0xffu, s, o);
        if (tid == 0) red[0] = s;
    }
    __syncthreads();
    float inv = rsqrtf(red[0] * (1.0f / 256.0f) + 1e-6f);
    buf[tid] = v * inv * w[tid];
    __syncthreads();

    int sub = tid >> 7, d = tid & 127;
    const float* base = buf + (sub << 7);
    int j = (d < 64) ? d : d - 64;
    float c = cosp[t * 64 + j], s = sinp[t * 64 + j];
    float x1 = base[2 * j], x2 = base[2 * j + 1];
    float o = (d < 64) ? (x1 * c - x2 * s) : (x1 * s + x2 * c);
    out[t * QDIM + (h * 2 + sub) * HD + d] = __float2half(o);
}

// ---------------------------------------------------------------------------
// K rmsnorm (over 128) + rope, fp16 out. grid (TSEQ,8), 128 threads.
// ---------------------------------------------------------------------------
__global__ void knorm_rope_kernel(
    const float* __restrict__ k, const float* __restrict__ w,
    const float* __restrict__ sinp, const float* __restrict__ cosp,
    __half* __restrict__ out)
{
    const int t = blockIdx.x, h = blockIdx.y;
    const int tid = threadIdx.x;
    __shared__ float buf[128];
    __shared__ float red[4];

    float v = k[t * KVDIM + h * HD + tid];
    float ss = v * v;
#pragma unroll
    for (int o = 16; o > 0; o >>= 1) ss += __shfl_down_sync(0xffffffffu, ss, o);
    if ((tid & 31) == 0) red[tid >> 5] = ss;
    __syncthreads();
    if (tid < 4) {
        float s = red[tid];
#pragma unroll
        for (int o = 2; o > 0; o >>= 1) s += __shfl_down_sync(0xfu, s, o);
        if (tid == 0) red[0] = s;
    }
    __syncthreads();
    float inv = rsqrtf(red[0] * (1.0f / 128.0f) + 1e-6f);
    buf[tid] = v * inv * w[tid];
    __syncthreads();

    int d = tid;
    int j = (d < 64) ? d : d - 64;
    float c = cosp[t * 64 + j], s = sinp[t * 64 + j];
    float x1 = buf[2 * j], x2 = buf[2 * j + 1];
    float o = (d < 64) ? (x1 * c - x2 * s) : (x1 * s + x2 * c);
    out[t * KVDIM + h * HD + d] = __float2half(o);
}

// ---------------------------------------------------------------------------
// Launch
// ---------------------------------------------------------------------------
extern "C" void kernel_launch(void* const* d_in, const int* in_sizes, int n_in,
                              void* d_out, int out_size)
{
    const float* x    = (const float*)d_in[0];
    const float* Wq   = (const float*)d_in[1];
    const float* Wk   = (const float*)d_in[2];
    const float* Wv   = (const float*)d_in[3];
    const float* Wo   = (const float*)d_in[4];
    const float* qw   = (const float*)d_in[5];
    const float* kw   = (const float*)d_in[6];
    const float* sinp = (const float*)d_in[7];
    const float* cosp = (const float*)d_in[8];
    float* out = (float*)d_out;

    float *pq, *pk, *pv, *ps;
    __half *px16, *pqr, *pkr, *patt, *pwqt, *pwkt, *pwvt, *pwot, *pvt, *pp;
    cudaGetSymbolAddress((void**)&px16, g_x16);
    cudaGetSymbolAddress((void**)&pq,   g_q);
    cudaGetSymbolAddress((void**)&pk,   g_k);
    cudaGetSymbolAddress((void**)&pv,   g_v);
    cudaGetSymbolAddress((void**)&pqr,  g_qr);
    cudaGetSymbolAddress((void**)&pkr,  g_kr);
    cudaGetSymbolAddress((void**)&patt, g_att);
    cudaGetSymbolAddress((void**)&pwqt, g_wqt);
    cudaGetSymbolAddress((void**)&pwkt, g_wkt);
    cudaGetSymbolAddress((void**)&pwvt, g_wvt);
    cudaGetSymbolAddress((void**)&pwot, g_wot);
    cudaGetSymbolAddress((void**)&pvt,  g_vt);
    cudaGetSymbolAddress((void**)&ps,   g_s);
    cudaGetSymbolAddress((void**)&pp,   g_p);

    cudaFuncSetAttribute(gemm_h<0>, cudaFuncAttributeMaxDynamicSharedMemorySize,
                         GEMM_SMEM);
    cudaFuncSetAttribute(gemm_h<1>, cudaFuncAttributeMaxDynamicSharedMemorySize,
                         GEMM_SMEM);

    dim3 tb(32, 8);
    // x -> fp16
    cvt16<<<(TSEQ * HID) / 1024, 256>>>(x, px16);

    // Weight transposes to [N,K] half
    transpose_h<<<dim3(QDIM / 32, HID / 32), tb>>>(Wq, pwqt, HID, QDIM);
    transpose_h<<<dim3(KVDIM / 32, HID / 32), tb>>>(Wk, pwkt, HID, KVDIM);
    transpose_h<<<dim3(KVDIM / 32, HID / 32), tb>>>(Wv, pwvt, HID, KVDIM);
    transpose_h<<<dim3(HID / 32, QDIM / 32), tb>>>(Wo, pwot, QDIM, HID);

    // Projections (fp16 x fp16 -> fp32)
    gemm_h<0><<<dim3(QDIM / BN, TSEQ / BM, 1), 256, GEMM_SMEM>>>(
        px16, pwqt, pq, HID, HID, HID, QDIM, 0, 0, 0, 0);
    gemm_h<0><<<dim3(KVDIM / BN, TSEQ / BM, 1), 256, GEMM_SMEM>>>(
        px16, pwkt, pk, HID, HID, HID, KVDIM, 0, 0, 0, 0);
    gemm_h<0><<<dim3(KVDIM / BN, TSEQ / BM, 1), 256, GEMM_SMEM>>>(
        px16, pwvt, pv, HID, HID, HID, KVDIM, 0, 0, 0, 0);

    // Norm + rope (fp16 outputs)
    qnorm_rope_kernel<<<dim3(TSEQ, NH16), 256>>>(pq, qw, sinp, cosp, pqr);
    knorm_rope_kernel<<<dim3(TSEQ, NKV), 128>>>(pk, kw, sinp, cosp, pkr);

    // V^T (fp16) for PV gemm B operand
    transpose_h<<<dim3(KVDIM / 32, TSEQ / 32), tb>>>(pv, pvt, TSEQ, KVDIM);

    // S = Q K^T per head (raw logits, fp32), batched over 32 heads
    gemm_h<0><<<dim3(TSEQ / BN, TSEQ / BM, HQ), 256, GEMM_SMEM>>>(
        pqr, pkr, ps, HD, QDIM, KVDIM, TSEQ,
        (long long)HD, (long long)HD, (long long)TSEQ * TSEQ, 2);

    // softmax rows -> fp16 P
    softmax_kernel<<<(HQ * TSEQ) / 8, 256>>>(ps, pp);

    // O = P V per head (fp16 P x fp16 V^T -> fp16 att)
    gemm_h<1><<<dim3(HD / BN, TSEQ / BM, HQ), 256, GEMM_SMEM>>>(
        pp, pvt, patt, TSEQ, TSEQ, TSEQ, QDIM,
        (long long)TSEQ * TSEQ, (long long)HD * TSEQ, (long long)HD, 2);

    // Output projection (fp16 att x fp16 Wo^T -> fp32 out)
    gemm_h<0><<<dim3(HID / BN, TSEQ / BM, 1), 256, GEMM_SMEM>>>(
        patt, pwot, out, QDIM, QDIM, QDIM, HID, 0, 0, 0, 0);
}

// round 14
// speedup vs baseline: 1.3898x; 1.1142x over previous
#include <cuda_runtime.h>
#include <cuda_fp16.h>
#include <cstdint>
#include <math.h>

// ---------------------------------------------------------------------------
// Problem constants
// ---------------------------------------------------------------------------
#define TSEQ   2048
#define HID    2048
#define QDIM   4096   // 32 rope-heads * 128
#define KVDIM  1024   // 8 kv heads * 128
#define QKVDIM 6144   // QDIM + 2*KVDIM (merged projection width)
#define HD     128
#define NH16   16
#define NKV    8
#define HQ     32

#define ATT_SCALE 0.08838834764831845f   // 1/sqrt(128)

// ---------------------------------------------------------------------------
// Static device scratch (no allocations allowed)
// ---------------------------------------------------------------------------
__device__ __half   g_x16 [TSEQ * HID];
__device__ __half   g_wqkv[QKVDIM * HID];     // merged [Wq;Wk;Wv]^T, K-major
__device__ float    g_qkv [TSEQ * QKVDIM];    // merged q|k|v fp32
__device__ __half   g_qr  [TSEQ * QDIM];
__device__ __half   g_kr  [TSEQ * KVDIM];
__device__ __half   g_att [TSEQ * QDIM];
__device__ __half   g_wot [HID * QDIM];
__device__ __half   g_vt  [KVDIM * TSEQ];
__device__ float    g_s   [134217728];        // 32 * 2048 * 2048 fp32 S
__device__ __half   g_p   [134217728];        // 32 * 2048 * 2048 fp16 P

// ---------------------------------------------------------------------------
// Helpers
// ---------------------------------------------------------------------------
__device__ __forceinline__ uint32_t pk_h2(float a, float b) {
    __half2 h = __floats2half2_rn(a, b);
    return *reinterpret_cast<uint32_t*>(&h);
}

__device__ __forceinline__ uint32_t smem_u32(const void* p) {
    uint32_t a;
    asm("{ .reg .u64 t; cvta.to.shared.u64 t, %1; cvt.u32.u64 %0, t; }"
        : "=r"(a) : "l"(p));
    return a;
}

__device__ __forceinline__ void mma_f16(
    float& d0, float& d1, float& d2, float& d3,
    uint32_t a0, uint32_t a1, uint32_t a2, uint32_t a3,
    uint32_t b0, uint32_t b1)
{
    asm volatile(
        "mma.sync.aligned.m16n8k16.row.col.f32.f16.f16.f32 "
        "{%0,%1,%2,%3}, {%4,%5,%6,%7}, {%8,%9}, {%0,%1,%2,%3};"
        : "+f"(d0), "+f"(d1), "+f"(d2), "+f"(d3)
        : "r"(a0), "r"(a1), "r"(a2), "r"(a3), "r"(b0), "r"(b1));
}

__device__ __forceinline__ void ldsm4(
    uint32_t& r0, uint32_t& r1, uint32_t& r2, uint32_t& r3, uint32_t addr)
{
    asm volatile(
        "ldmatrix.sync.aligned.m8n8.x4.shared.b16 {%0,%1,%2,%3}, [%4];"
        : "=r"(r0), "=r"(r1), "=r"(r2), "=r"(r3) : "r"(addr));
}

__device__ __forceinline__ void cp16(uint32_t dst, const void* src) {
    asm volatile("cp.async.cg.shared.global [%0], [%1], 16;"
                 :: "r"(dst), "l"(src));
}
#define CP_COMMIT() asm volatile("cp.async.commit_group;" ::: "memory")
#define CP_WAIT0()  asm volatile("cp.async.wait_group 0;" ::: "memory")
#define CP_WAIT1()  asm volatile("cp.async.wait_group 1;" ::: "memory")

// ---------------------------------------------------------------------------
// All-fp16 mma.sync GEMM: C[M,N] = A[M,K] @ B[N,K]^T
// A, B row-major fp16 (K-major). 128x128 CTA tile, BK=32, 8 warps.
// 3-stage cp.async pipeline, ONE __syncthreads per K-iteration,
// ldmatrix.x4 fragment loads. OUTH=1 -> C fp16, else fp32.
// Batched via blockIdx.z. M, N multiples of 128; K multiple of 32 (>=128).
// ---------------------------------------------------------------------------
#define BM 128
#define BN 128
#define AWS 20      // half2-word row stride: 16 data + 4 pad
#define STG_A (BM * AWS * 4)                 // bytes per A stage
#define STG_B (BN * AWS * 4)                 // bytes per B stage
#define GEMM_SMEM (3 * (STG_A + STG_B))      // 61440 B

template <int OUTH>
__global__ __launch_bounds__(256) void gemm_h(
    const __half* __restrict__ A, const __half* __restrict__ B,
    void* __restrict__ Cv, int K, int lda, int ldb, int ldc,
    long long bsA, long long bsB, long long bsC, int bshift)
{
    extern __shared__ uint32_t sm[];

    const int z = blockIdx.z;
    A += (long long)z * bsA;
    B += (long long)(z >> bshift) * bsB;

    const int tid  = threadIdx.x;
    const int wid  = tid >> 5;
    const int lane = tid & 31;
    const int m0 = blockIdx.y * BM;
    const int n0 = blockIdx.x * BN;

    const int wm = (wid >> 2) * 64;
    const int wn = (wid & 3) * 32;
    const int g  = lane >> 2;
    const int t  = lane & 3;

    const uint32_t smb  = smem_u32(sm);
    const uint32_t bsmb = smb + 3 * STG_A;

    // ldmatrix lane address components (validated in R11)
    const int l7  = lane & 7;
    const int sel = lane >> 3;
    const uint32_t a_lane = ((l7 + ((sel & 1) << 3)) * AWS + ((sel >> 1) << 2)) * 4;
    const uint32_t b_lane = ((l7 + ((sel >> 1) << 3)) * AWS + ((sel & 1) << 2)) * 4;

    float acc[4][4][4];
#pragma unroll
    for (int mt = 0; mt < 4; mt++)
#pragma unroll
        for (int nt = 0; nt < 4; nt++)
#pragma unroll
            for (int r = 0; r < 4; r++) acc[mt][nt][r] = 0.0f;

    // cp.async mapping: 4 chunks/thread/stage (2 A rows + 2 B rows)
    const int r0c = tid >> 2;          // row (+64 for second chunk)
    const int off = (tid & 3);         // 16B unit within 32-half row
    const uint32_t dlo = (uint32_t)((r0c * AWS + (off << 2)) << 2);
    const uint32_t dhi = (uint32_t)(((r0c + 64) * AWS + (off << 2)) << 2);
    const __half* arow0 = A + (size_t)(m0 + r0c) * lda + (off << 3);
    const __half* arow1 = arow0 + (size_t)64 * lda;
    const __half* brow0 = B + (size_t)(n0 + r0c) * ldb + (off << 3);
    const __half* brow1 = brow0 + (size_t)64 * ldb;

    const int nk = K >> 5;

    // prologue: stages 0, 1
#pragma unroll
    for (int s = 0; s < 2; s++) {
        const int k0 = s << 5;
        const uint32_t as_u = smb + s * STG_A;
        const uint32_t bs_u = bsmb + s * STG_B;
        cp16(as_u + dlo, arow0 + k0);
        cp16(as_u + dhi, arow1 + k0);
        cp16(bs_u + dlo, brow0 + k0);
        cp16(bs_u + dhi, brow1 + k0);
        CP_COMMIT();
    }

    int stage = 0;
    for (int kt = 0; kt < nk; kt++) {
        if (kt + 1 < nk) { CP_WAIT1(); } else { CP_WAIT0(); }
        __syncthreads();

        // issue loads for stage kt+2 (buffer freed by the sync above)
        if (kt + 2 < nk) {
            const int s2 = (stage + 2 >= 3) ? stage - 1 : stage + 2;
            const int k0 = (kt + 2) << 5;
            const uint32_t as_u = smb + s2 * STG_A;
            const uint32_t bs_u = bsmb + s2 * STG_B;
            cp16(as_u + dlo, arow0 + k0);
            cp16(as_u + dhi, arow1 + k0);
            cp16(bs_u + dlo, brow0 + k0);
            cp16(bs_u + dhi, brow1 + k0);
            CP_COMMIT();
        }

        const uint32_t as_b = smb + stage * STG_A;
        const uint32_t bs_b = bsmb + stage * STG_B;

#pragma unroll
        for (int kc = 0; kc < 2; kc++) {
            const uint32_t kw = (kc * 8) * 4;
            uint32_t af[4][4], bf[4][2];
#pragma unroll
            for (int mt = 0; mt < 4; mt++)
                ldsm4(af[mt][0], af[mt][1], af[mt][2], af[mt][3],
                      as_b + ((wm + mt * 16) * AWS) * 4 + kw + a_lane);
#pragma unroll
            for (int np = 0; np < 2; np++)
                ldsm4(bf[2 * np][0], bf[2 * np][1],
                      bf[2 * np + 1][0], bf[2 * np + 1][1],
                      bs_b + ((wn + np * 16) * AWS) * 4 + kw + b_lane);
#pragma unroll
            for (int mt = 0; mt < 4; mt++)
#pragma unroll
                for (int nt = 0; nt < 4; nt++)
                    mma_f16(acc[mt][nt][0], acc[mt][nt][1],
                            acc[mt][nt][2], acc[mt][nt][3],
                            af[mt][0], af[mt][1], af[mt][2], af[mt][3],
                            bf[nt][0], bf[nt][1]);
        }
        stage = (stage + 1 >= 3) ? 0 : stage + 1;
    }

    // Epilogue
    if (OUTH) {
        __half* C = (__half*)Cv + (long long)z * bsC;
#pragma unroll
        for (int mt = 0; mt < 4; mt++) {
            const int row = m0 + wm + mt * 16 + g;
#pragma unroll
            for (int nt = 0; nt < 4; nt++) {
                const int col = n0 + wn + nt * 8 + 2 * t;
                *(uint32_t*)(C + (size_t)row * ldc + col) =
                    pk_h2(acc[mt][nt][0], acc[mt][nt][1]);
                *(uint32_t*)(C + (size_t)(row + 8) * ldc + col) =
                    pk_h2(acc[mt][nt][2], acc[mt][nt][3]);
            }
        }
    } else {
        float* C = (float*)Cv + (long long)z * bsC;
#pragma unroll
        for (int mt = 0; mt < 4; mt++) {
            const int row = m0 + wm + mt * 16 + g;
#pragma unroll
            for (int nt = 0; nt < 4; nt++) {
                const int col = n0 + wn + nt * 8 + 2 * t;
                *(float2*)(C + (size_t)row * ldc + col) =
                    make_float2(acc[mt][nt][0], acc[mt][nt][1]);
                *(float2*)(C + (size_t)(row + 8) * ldc + col) =
                    make_float2(acc[mt][nt][2], acc[mt][nt][3]);
            }
        }
    }
}

// ---------------------------------------------------------------------------
// fp32 -> fp16 convert (x), vectorized
// ---------------------------------------------------------------------------
__global__ void cvt16(const float* __restrict__ in, __half* __restrict__ out)
{
    const int i = (blockIdx.x * 256 + threadIdx.x) << 2;
    float4 v = *(const float4*)(in + i);
    uint2 o = make_uint2(pk_h2(v.x, v.y), pk_h2(v.z, v.w));
    *(uint2*)(out + i) = o;
}

// ---------------------------------------------------------------------------
// Tiled transpose fp32 -> fp16 with input stride:
// out[x][y] = half(in[y*ldin + x]),  x in [0,C), y in [0,R-ish covered by grid)
// out stride = R (out is [C, R])
// ---------------------------------------------------------------------------
__global__ void transpose_h(const float* __restrict__ in,
                            __half* __restrict__ out, int R, int C, int ldin)
{
    __shared__ float t[32][33];
    const int x = blockIdx.x * 32 + threadIdx.x;
    const int y0 = blockIdx.y * 32 + threadIdx.y;
#pragma unroll
    for (int j = 0; j < 32; j += 8)
        t[threadIdx.y + j][threadIdx.x] = in[(size_t)(y0 + j) * ldin + x];
    __syncthreads();
    const int x2 = blockIdx.y * 32 + threadIdx.x;
    const int y2 = blockIdx.x * 32 + threadIdx.y;
#pragma unroll
    for (int j = 0; j < 32; j += 8)
        out[(size_t)(y2 + j) * R + x2] = __float2half(t[threadIdx.x][threadIdx.y + j]);
}

// ---------------------------------------------------------------------------
// Row softmax: read fp32 S, write fp16 P (scale folded). 1 warp / row.
// ---------------------------------------------------------------------------
__global__ __launch_bounds__(256) void softmax_kernel(
    const float* __restrict__ S, __half* __restrict__ P)
{
    const int row = blockIdx.x * 8 + (threadIdx.x >> 5);
    const int lane = threadIdx.x & 31;
    const float* p = S + (size_t)row * 2048 + lane * 4;
    __half* q = P + (size_t)row * 2048 + lane * 4;

    float4 v[16];
#pragma unroll
    for (int w = 0; w < 16; w++) v[w] = *(const float4*)(p + w * 128);

    float m = -1e30f;
#pragma unroll
    for (int w = 0; w < 16; w++)
        m = fmaxf(m, fmaxf(fmaxf(v[w].x, v[w].y), fmaxf(v[w].z, v[w].w)));
#pragma unroll
    for (int o = 16; o > 0; o >>= 1)
        m = fmaxf(m, __shfl_xor_sync(0xffffffffu, m, o));

    const float ms = m * ATT_SCALE;
    float sum = 0.0f;
#pragma unroll
    for (int w = 0; w < 16; w++) {
        v[w].x = __expf(fmaf(v[w].x, ATT_SCALE, -ms));
        v[w].y = __expf(fmaf(v[w].y, ATT_SCALE, -ms));
        v[w].z = __expf(fmaf(v[w].z, ATT_SCALE, -ms));
        v[w].w = __expf(fmaf(v[w].w, ATT_SCALE, -ms));
        sum += (v[w].x + v[w].y) + (v[w].z + v[w].w);
    }
#pragma unroll
    for (int o = 16; o > 0; o >>= 1)
        sum += __shfl_xor_sync(0xffffffffu, sum, o);

    const float inv = 1.0f / sum;
#pragma unroll
    for (int w = 0; w < 16; w++) {
        uint2 o2 = make_uint2(pk_h2(v[w].x * inv, v[w].y * inv),
                              pk_h2(v[w].z * inv, v[w].w * inv));
        *(uint2*)(q + w * 128) = o2;
    }
}

// ---------------------------------------------------------------------------
// Q rmsnorm (over 256) + rope, fp16 out. grid (TSEQ,16), 256 threads.
// Reads q from strided slice (ld = QKVDIM).
// ---------------------------------------------------------------------------
__global__ void qnorm_rope_kernel(
    const float* __restrict__ q, int ld, const float* __restrict__ w,
    const float* __restrict__ sinp, const float* __restrict__ cosp,
    __half* __restrict__ out)
{
    const int t = blockIdx.x, h = blockIdx.y;
    const int tid = threadIdx.x;
    __shared__ float buf[256];
    __shared__ float red[8];

    float v = q[(size_t)t * ld + h * 256 + tid];
    float ss = v * v;
#pragma unroll
    for (int o = 16; o > 0; o >>= 1) ss += __shfl_down_sync(0xffffffffu, ss, o);
    if ((tid & 31) == 0) red[tid >> 5] = ss;
    __syncthreads();
    if (tid < 8) {
        float s = red[tid];
#pragma unroll
        for (int o = 4; o > 0; o >>= 1) s += __shfl_down_sync(0xffu, s, o);
        if (tid == 0) red[0] = s;
    }
    __syncthreads();
    float inv = rsqrtf(red[0] * (1.0f / 256.0f) + 1e-6f);
    buf[tid] = v * inv * w[tid];
    __syncthreads();

    int sub = tid >> 7, d = tid & 127;
    const float* base = buf + (sub << 7);
    int j = (d < 64) ? d : d - 64;
    float c = cosp[t * 64 + j], s = sinp[t * 64 + j];
    float x1 = base[2 * j], x2 = base[2 * j + 1];
    float o = (d < 64) ? (x1 * c - x2 * s) : (x1 * s + x2 * c);
    out[t * QDIM + (h * 2 + sub) * HD + d] = __float2half(o);
}

// ---------------------------------------------------------------------------
// K rmsnorm (over 128) + rope, fp16 out. grid (TSEQ,8), 128 threads.
// Reads k from strided slice (ld = QKVDIM).
// ---------------------------------------------------------------------------
__global__ void knorm_rope_kernel(
    const float* __restrict__ k, int ld, const float* __restrict__ w,
    const float* __restrict__ sinp, const float* __restrict__ cosp,
    __half* __restrict__ out)
{
    const int t = blockIdx.x, h = blockIdx.y;
    const int tid = threadIdx.x;
    __shared__ float buf[128];
    __shared__ float red[4];

    float v = k[(size_t)t * ld + h * HD + tid];
    float ss = v * v;
#pragma unroll
    for (int o = 16; o > 0; o >>= 1) ss += __shfl_down_sync(0xffffffffu, ss, o);
    if ((tid & 31) == 0) red[tid >> 5] = ss;
    __syncthreads();
    if (tid < 4) {
        float s = red[tid];
#pragma unroll
        for (int o = 2; o > 0; o >>= 1) s += __shfl_down_sync(0xfu, s, o);
        if (tid == 0) red[0] = s;
    }
    __syncthreads();
    float inv = rsqrtf(red[0] * (1.0f / 128.0f) + 1e-6f);
    buf[tid] = v * inv * w[tid];
    __syncthreads();

    int d = tid;
    int j = (d < 64) ? d : d - 64;
    float c = cosp[t * 64 + j], s = sinp[t * 64 + j];
    float x1 = buf[2 * j], x2 = buf[2 * j + 1];
    float o = (d < 64) ? (x1 * c - x2 * s) : (x1 * s + x2 * c);
    out[t * KVDIM + h * HD + d] = __float2half(o);
}

// ---------------------------------------------------------------------------
// Launch
// ---------------------------------------------------------------------------
extern "C" void kernel_launch(void* const* d_in, const int* in_sizes, int n_in,
                              void* d_out, int out_size)
{
    const float* x    = (const float*)d_in[0];
    const float* Wq   = (const float*)d_in[1];
    const float* Wk   = (const float*)d_in[2];
    const float* Wv   = (const float*)d_in[3];
    const float* Wo   = (const float*)d_in[4];
    const float* qw   = (const float*)d_in[5];
    const float* kw   = (const float*)d_in[6];
    const float* sinp = (const float*)d_in[7];
    const float* cosp = (const float*)d_in[8];
    float* out = (float*)d_out;

    float *pqkv, *ps;
    __half *px16, *pwqkv, *pqr, *pkr, *patt, *pwot, *pvt, *pp;
    cudaGetSymbolAddress((void**)&px16,  g_x16);
    cudaGetSymbolAddress((void**)&pwqkv, g_wqkv);
    cudaGetSymbolAddress((void**)&pqkv,  g_qkv);
    cudaGetSymbolAddress((void**)&pqr,   g_qr);
    cudaGetSymbolAddress((void**)&pkr,   g_kr);
    cudaGetSymbolAddress((void**)&patt,  g_att);
    cudaGetSymbolAddress((void**)&pwot,  g_wot);
    cudaGetSymbolAddress((void**)&pvt,   g_vt);
    cudaGetSymbolAddress((void**)&ps,    g_s);
    cudaGetSymbolAddress((void**)&pp,    g_p);

    cudaFuncSetAttribute(gemm_h<0>, cudaFuncAttributeMaxDynamicSharedMemorySize,
                         GEMM_SMEM);
    cudaFuncSetAttribute(gemm_h<1>, cudaFuncAttributeMaxDynamicSharedMemorySize,
                         GEMM_SMEM);

    dim3 tb(32, 8);
    // x -> fp16
    cvt16<<<(TSEQ * HID) / 1024, 256>>>(x, px16);

    // Weight transposes into merged [6144, 2048] (Wq | Wk | Wv) + Wo
    transpose_h<<<dim3(QDIM / 32, HID / 32), tb>>>(Wq, pwqkv, HID, QDIM, QDIM);
    transpose_h<<<dim3(KVDIM / 32, HID / 32), tb>>>(
        Wk, pwqkv + (size_t)QDIM * HID, HID, KVDIM, KVDIM);
    transpose_h<<<dim3(KVDIM / 32, HID / 32), tb>>>(
        Wv, pwqkv + (size_t)(QDIM + KVDIM) * HID, HID, KVDIM, KVDIM);
    transpose_h<<<dim3(HID / 32, QDIM / 32), tb>>>(Wo, pwot, QDIM, HID, HID);

    // Merged QKV projection: [2048, 2048] @ [6144, 2048]^T -> [2048, 6144] fp32
    gemm_h<0><<<dim3(QKVDIM / BN, TSEQ / BM, 1), 256, GEMM_SMEM>>>(
        px16, pwqkv, pqkv, HID, HID, HID, QKVDIM, 0, 0, 0, 0);

    // Norm + rope (fp16 outputs), reading strided slices of qkv
    qnorm_rope_kernel<<<dim3(TSEQ, NH16), 256>>>(
        pqkv, QKVDIM, qw, sinp, cosp, pqr);
    knorm_rope_kernel<<<dim3(TSEQ, NKV), 128>>>(
        pqkv + QDIM, QKVDIM, kw, sinp, cosp, pkr);

    // V^T (fp16) from the v slice of qkv
    transpose_h<<<dim3(KVDIM / 32, TSEQ / 32), tb>>>(
        pqkv + QDIM + KVDIM, pvt, TSEQ, KVDIM, QKVDIM);

    // S = Q K^T per head (raw logits, fp32), batched over 32 heads
    gemm_h<0><<<dim3(TSEQ / BN, TSEQ / BM, HQ), 256, GEMM_SMEM>>>(
        pqr, pkr, ps, HD, QDIM, KVDIM, TSEQ,
        (long long)HD, (long long)HD, (long long)TSEQ * TSEQ, 2);

    // softmax rows -> fp16 P
    softmax_kernel<<<(HQ * TSEQ) / 8, 256>>>(ps, pp);

    // O = P V per head (fp16 P x fp16 V^T -> fp16 att)
    gemm_h<1><<<dim3(HD / BN, TSEQ / BM, HQ), 256, GEMM_SMEM>>>(
        pp, pvt, patt, TSEQ, TSEQ, TSEQ, QDIM,
        (long long)TSEQ * TSEQ, (long long)HD * TSEQ, (long long)HD, 2);

    // Output projection (fp16 att x fp16 Wo^T -> fp32 out)
    gemm_h<0><<<dim3(HID / BN, TSEQ / BM, 1), 256, GEMM_SMEM>>>(
        patt, pwot, out, QDIM, QDIM, QDIM, HID, 0, 0, 0, 0);
}